// round 15
// baseline (speedup 1.0000x reference)
#include <cuda_runtime.h>
#include <cuda_bf16.h>
#include <cstdint>

// Problem constants
#define NROWS   131072
#define KDIM    512
#define CMREAL  190
#define CMPAD   192
#define LAMDA   (1.0f/256.0f)

#define TILE_M    64
#define THREADS   256
#define NCHUNKS   8           // K chunks of 64
#define ACH_BYTES 8192        // A chunk: 64 rows x 128B
#define BCH_BYTES 24576       // B chunk: 192 rows x 128B
#define NSTAGE    3

// SMEM layout (from 1024-aligned base)
#define OFF_RS   0            // 64 floats
#define OFF_CB   512          // 192 floats
#define OFF_A0   2048                           // 3 x 8192
#define OFF_B0   (OFF_A0 + NSTAGE * ACH_BYTES)  // 26624, 3 x 24576
#define SMEM_NEED (OFF_B0 + NSTAGE * BCH_BYTES) // 100352
#define SMEM_REQ  (SMEM_NEED + 1024)            // 101376 (<= 116KB/CTA at occ 2)

__device__ __align__(16) uint8_t g_B[NCHUNKS * BCH_BYTES];
__device__ float g_colbias[CMPAD];

// ---------------- helpers ----------------
__device__ __forceinline__ uint32_t smem_u32(const void* p) {
    uint32_t a;
    asm("{ .reg .u64 t; cvta.to.shared.u64 t, %1; cvt.u32.u64 %0, t; }" : "=r"(a) : "l"(p));
    return a;
}

__device__ __forceinline__ float fsqrt_ap(float x) {
    float r; asm("sqrt.approx.f32 %0, %1;" : "=f"(r) : "f"(x)); return r;
}

__device__ __forceinline__ void ldm_x4(uint32_t* r, uint32_t addr) {
    asm volatile("ldmatrix.sync.aligned.m8n8.x4.shared.b16 {%0,%1,%2,%3}, [%4];"
                 : "=r"(r[0]), "=r"(r[1]), "=r"(r[2]), "=r"(r[3]) : "r"(addr));
}

__device__ __forceinline__ void mma16816(float* c, const uint32_t* a, uint32_t b0, uint32_t b1) {
    asm volatile("mma.sync.aligned.m16n8k16.row.col.f32.bf16.bf16.f32 "
                 "{%0,%1,%2,%3}, {%4,%5,%6,%7}, {%8,%9}, {%0,%1,%2,%3};"
                 : "+f"(c[0]), "+f"(c[1]), "+f"(c[2]), "+f"(c[3])
                 : "r"(a[0]), "r"(a[1]), "r"(a[2]), "r"(a[3]), "r"(b0), "r"(b1));
}

#define CP_ASYNC16(dst, src) \
    asm volatile("cp.async.cg.shared.global [%0], [%1], 16;" \
                 :: "r"(dst), "l"(src) : "memory")
#define CP_COMMIT()  asm volatile("cp.async.commit_group;" ::: "memory")
#define CP_WAIT1()   asm volatile("cp.async.wait_group 1;" ::: "memory")
#define CP_WAIT0()   asm volatile("cp.async.wait_group 0;" ::: "memory")

#define STS64(addr, v) \
    asm volatile("st.shared.b64 [%0], %1;" :: "r"(addr), "l"(v) : "memory")

// swizzled byte offset within a [rows x 128B] K-major bf16 tile:
// 16B unit u of row r goes to u ^ (r & 7)
__device__ __forceinline__ uint32_t swz_off(int r, int cb) {
    int u = cb >> 4;
    return (uint32_t)(r * 128 + (((u ^ (r & 7)) & 7) << 4) + (cb & 15));
}

__device__ __forceinline__ uint64_t pack_bf16x4(float a, float b, float c, float d) {
    __nv_bfloat162 lo = __floats2bfloat162_rn(a, b);
    __nv_bfloat162 hi = __floats2bfloat162_rn(c, d);
    uint32_t ulo = *(uint32_t*)&lo, uhi = *(uint32_t*)&hi;
    return (uint64_t)ulo | ((uint64_t)uhi << 32);
}

// ---------------- prep: pre-swizzled B + col biases (warp-parallel) ----------------
__global__ void prep_kernel(const float* __restrict__ pm, const float* __restrict__ pv) {
    int b = blockIdx.x, tid = threadIdx.x;
    if (b < 96) {
        int base = b * 1024;
        #pragma unroll
        for (int t = 0; t < 4; ++t) {
            int idx = base + t * 256 + tid;       // over 192*512
            int j = idx >> 9, d = idx & 511;
            float val = 0.0f;
            if (j < CMREAL)
                val = (d < 256) ? pm[j * 256 + d] : LAMDA * sqrtf(pv[j * 256 + (d - 256)]);
            int kc = d >> 6, k = d & 63;
            uint32_t off = swz_off(j, k * 2);
            *(__nv_bfloat16*)(g_B + kc * BCH_BYTES + off) = __float2bfloat16(val);
        }
    } else {
        // one warp per proto row j: lanes sum 8 elems each, shfl-reduce
        int wid = tid >> 5, lid = tid & 31;
        int j = (b - 96) * 8 + wid;               // 25 blocks x 8 warps = 200 >= 192
        if (j < CMPAD) {
            if (j < CMREAL) {
                const float2* p = (const float2*)(pv + j * 256);
                float2 v0 = p[lid * 4 + 0], v1 = p[lid * 4 + 1];
                float2 v2 = p[lid * 4 + 2], v3 = p[lid * 4 + 3];
                float s = v0.x + v0.y + v1.x + v1.y + v2.x + v2.y + v3.x + v3.y;
                #pragma unroll
                for (int o = 16; o > 0; o >>= 1)
                    s += __shfl_xor_sync(0xffffffffu, s, o);
                if (lid == 0) g_colbias[j] = -2.0f - LAMDA * s;
            } else if (lid == 0) {
                g_colbias[j] = 0.0f;
            }
        }
    }
}

// ---------------- main kernel: 3-stage pipeline ----------------
extern __shared__ char smem_raw[];

__global__ void __launch_bounds__(THREADS, 2)
wasserstein_kernel(const float* __restrict__ x, const float* __restrict__ xv,
                   float* __restrict__ out) {
    const int tid = threadIdx.x;
    const int wid = tid >> 5;
    const int lid = tid & 31;
    const int warp_m = wid & 1;   // 2 x 32 rows
    const int warp_n = wid >> 1;  // 4 x 48 cols
    const int row0 = blockIdx.x * TILE_M;

    uint32_t sraw = smem_u32(smem_raw);
    uint32_t sbase = (sraw + 1023u) & ~1023u;
    char* smp = smem_raw + (sbase - sraw);

    float* sm_rs = (float*)(smp + OFF_RS);
    float* sm_cb = (float*)(smp + OFF_CB);
    const uint32_t uA[NSTAGE] = { sbase + OFF_A0, sbase + OFF_A0 + ACH_BYTES,
                                  sbase + OFF_A0 + 2 * ACH_BYTES };
    const uint32_t uB[NSTAGE] = { sbase + OFF_B0, sbase + OFF_B0 + BCH_BYTES,
                                  sbase + OFF_B0 + 2 * BCH_BYTES };

    if (tid < CMPAD) sm_cb[tid] = g_colbias[tid];

    const float4* x4 = (const float4*)x;
    const float4* v4 = (const float4*)xv;

    // per-thread A mapping: one row per thread-quad; 4 consecutive float4 each
    const int arow = tid >> 2;            // 0..63
    const int ac4  = (tid & 3) * 4;       // first float4 col within chunk (of 16)

    float acc[2][6][4];
    #pragma unroll
    for (int mi = 0; mi < 2; ++mi)
        #pragma unroll
        for (int nj = 0; nj < 6; ++nj)
            #pragma unroll
            for (int q = 0; q < 4; ++q) acc[mi][nj][q] = 0.0f;

    float4 aregs[4];
    float rsum = 0.0f;   // private partial row sum of x_var

    // ---- prologue: stage chunks 0 and 1 ----
    #pragma unroll
    for (int kp = 0; kp < 2; ++kp) {
        const size_t rb = (size_t)(row0 + arow) * 64 + kp * 16;
        #pragma unroll
        for (int i = 0; i < 4; ++i)
            aregs[i] = x4[rb + ac4 + i];
        const char* src = (const char*)g_B + kp * BCH_BYTES + tid * 16;
        #pragma unroll
        for (int i = 0; i < 6; ++i)
            CP_ASYNC16(uB[kp] + tid * 16 + i * 4096, src + i * 4096);
        CP_COMMIT();
        #pragma unroll
        for (int i = 0; i < 4; ++i) {
            uint32_t off = swz_off(arow, (ac4 + i) * 8);
            STS64(uA[kp] + off, pack_bf16x4(aregs[i].x, aregs[i].y, aregs[i].z, aregs[i].w));
        }
    }

    const int ra_base = warp_m * 32 + (lid & 15);
    const int a_uadd = lid >> 4;                       // +16B for hi K-half
    const int nb_base = warp_n * 48 + ((lid >> 4) << 3) + (lid & 7);
    const int b_uadd = (lid >> 3) & 1;

    // ---- main loop over 8 K-chunks, lookahead 2 ----
    int s_cur = 0, s_ld = 2;   // stage indices: consume, load-into
    for (int kc = 0; kc < NCHUNKS; ++kc) {
        if (kc < NCHUNKS - 1) CP_WAIT1(); else CP_WAIT0();
        __syncthreads();

        const bool have_next = (kc < NCHUNKS - 2);
        if (have_next) {
            const int kn = kc + 2;
            const float4* srcT = (kn < 4) ? x4 : v4;
            const size_t rb = (size_t)(row0 + arow) * 64 + (kn & 3) * 16;
            #pragma unroll
            for (int i = 0; i < 4; ++i)
                aregs[i] = srcT[rb + ac4 + i];
            const char* src = (const char*)g_B + kn * BCH_BYTES + tid * 16;
            #pragma unroll
            for (int i = 0; i < 6; ++i)
                CP_ASYNC16(uB[s_ld] + tid * 16 + i * 4096, src + i * 4096);
            CP_COMMIT();
        }

        // ---- MMA over chunk kc in stage s_cur ----
        {
            const uint32_t ua = uA[s_cur], ub = uB[s_cur];
            #pragma unroll
            for (int ks = 0; ks < 4; ++ks) {
                uint32_t af[2][4];
                #pragma unroll
                for (int mi = 0; mi < 2; ++mi) {
                    int r = ra_base + mi * 16;
                    int u = ks * 2 + a_uadd;
                    ldm_x4(af[mi], ua + r * 128 + (((u ^ (r & 7)) & 7) << 4));
                }
                #pragma unroll
                for (int njp = 0; njp < 3; ++njp) {
                    int n = nb_base + njp * 16;
                    int u = ks * 2 + b_uadd;
                    uint32_t bf[4];
                    ldm_x4(bf, ub + n * 128 + (((u ^ (n & 7)) & 7) << 4));
                    #pragma unroll
                    for (int mi = 0; mi < 2; ++mi) {
                        mma16816(acc[mi][2 * njp],     af[mi], bf[0], bf[1]);
                        mma16816(acc[mi][2 * njp + 1], af[mi], bf[2], bf[3]);
                    }
                }
            }
        }

        // ---- convert + STS A chunk kc+2 into stage s_ld ----
        if (have_next) {
            const bool isv = (kc + 2) >= 4;
            if (isv) {
                rsum += aregs[0].x + aregs[0].y + aregs[0].z + aregs[0].w
                      + aregs[1].x + aregs[1].y + aregs[1].z + aregs[1].w
                      + aregs[2].x + aregs[2].y + aregs[2].z + aregs[2].w
                      + aregs[3].x + aregs[3].y + aregs[3].z + aregs[3].w;
                #pragma unroll
                for (int i = 0; i < 4; ++i) {
                    aregs[i].x = fsqrt_ap(aregs[i].x); aregs[i].y = fsqrt_ap(aregs[i].y);
                    aregs[i].z = fsqrt_ap(aregs[i].z); aregs[i].w = fsqrt_ap(aregs[i].w);
                }
            }
            #pragma unroll
            for (int i = 0; i < 4; ++i) {
                uint32_t off = swz_off(arow, (ac4 + i) * 8);
                STS64(uA[s_ld] + off, pack_bf16x4(aregs[i].x, aregs[i].y, aregs[i].z, aregs[i].w));
            }
        }

        // rotate stages
        s_cur = (s_cur == NSTAGE - 1) ? 0 : s_cur + 1;
        s_ld  = (s_ld  == NSTAGE - 1) ? 0 : s_ld  + 1;
    }

    // finalize row sums: reduce the 4 threads sharing a row; single plain store
    rsum += __shfl_xor_sync(0xffffffffu, rsum, 1);
    rsum += __shfl_xor_sync(0xffffffffu, rsum, 2);
    if ((lid & 3) == 0) sm_rs[arow] = rsum;

    __syncthreads();   // rowsums visible; MMA done

    // ---- epilogue: biases + direct guarded STG.64 from fragment layout ----
    {
        const int gid = lid >> 2, qid = lid & 3;
        #pragma unroll
        for (int mi = 0; mi < 2; ++mi) {
            int r = warp_m * 32 + mi * 16 + gid;
            float rb0 = -LAMDA * sm_rs[r];
            float rb1 = -LAMDA * sm_rs[r + 8];
            size_t g0 = (size_t)(row0 + r) * CMREAL;
            size_t g1 = (size_t)(row0 + r + 8) * CMREAL;
            #pragma unroll
            for (int nj = 0; nj < 6; ++nj) {
                int c = warp_n * 48 + nj * 8 + qid * 2;
                if (c < CMREAL) {
                    float cb0 = sm_cb[c], cb1 = sm_cb[c + 1];
                    float2 v0 = make_float2(2.0f * acc[mi][nj][0] + rb0 + cb0,
                                            2.0f * acc[mi][nj][1] + rb0 + cb1);
                    float2 v1 = make_float2(2.0f * acc[mi][nj][2] + rb1 + cb0,
                                            2.0f * acc[mi][nj][3] + rb1 + cb1);
                    *(float2*)(out + g0 + c) = v0;
                    *(float2*)(out + g1 + c) = v1;
                }
            }
        }
    }
}

// ---------------- launch ----------------
extern "C" void kernel_launch(void* const* d_in, const int* in_sizes, int n_in,
                              void* d_out, int out_size) {
    const float* x  = (const float*)d_in[0];
    const float* xv = (const float*)d_in[1];
    const float* pm = (const float*)d_in[2];
    const float* pv = (const float*)d_in[3];
    float* out = (float*)d_out;

    cudaFuncSetAttribute(wasserstein_kernel,
                         cudaFuncAttributeMaxDynamicSharedMemorySize, SMEM_REQ);

    prep_kernel<<<121, 256>>>(pm, pv);
    wasserstein_kernel<<<NROWS / TILE_M, THREADS, SMEM_REQ>>>(x, xv, out);
}

// round 17
// speedup vs baseline: 1.1689x; 1.1689x over previous
#include <cuda_runtime.h>
#include <cuda_bf16.h>
#include <cstdint>

// Problem constants
#define NROWS   131072
#define KDIM    512
#define CMREAL  190
#define CMPAD   192
#define LAMDA   (1.0f/256.0f)

#define TILE_M    64
#define THREADS   256
#define NCHUNKS   8           // K chunks of 64
#define ACH_BYTES 8192        // A chunk: 64 rows x 128B
#define BCH_BYTES 24576       // B chunk: 192 rows x 128B

// SMEM layout (from 1024-aligned base)
#define OFF_RS   0            // 64 floats
#define OFF_CB   512          // 192 floats
#define OFF_A0   2048
#define OFF_A1   (OFF_A0 + ACH_BYTES)          // 10240
#define OFF_B0   (OFF_A1 + ACH_BYTES)          // 18432
#define OFF_B1   (OFF_B0 + BCH_BYTES)          // 43008
#define SMEM_NEED (OFF_B1 + BCH_BYTES)         // 67584
#define SMEM_REQ  (SMEM_NEED + 1024)

__device__ __align__(16) uint8_t g_B[NCHUNKS * BCH_BYTES];
__device__ float g_colbias[CMPAD];

// ---------------- helpers ----------------
__device__ __forceinline__ uint32_t smem_u32(const void* p) {
    uint32_t a;
    asm("{ .reg .u64 t; cvta.to.shared.u64 t, %1; cvt.u32.u64 %0, t; }" : "=r"(a) : "l"(p));
    return a;
}

__device__ __forceinline__ float fsqrt_ap(float x) {
    float r; asm("sqrt.approx.f32 %0, %1;" : "=f"(r) : "f"(x)); return r;
}

__device__ __forceinline__ void ldm_x4(uint32_t* r, uint32_t addr) {
    asm volatile("ldmatrix.sync.aligned.m8n8.x4.shared.b16 {%0,%1,%2,%3}, [%4];"
                 : "=r"(r[0]), "=r"(r[1]), "=r"(r[2]), "=r"(r[3]) : "r"(addr));
}

__device__ __forceinline__ void mma16816(float* c, const uint32_t* a, uint32_t b0, uint32_t b1) {
    asm volatile("mma.sync.aligned.m16n8k16.row.col.f32.bf16.bf16.f32 "
                 "{%0,%1,%2,%3}, {%4,%5,%6,%7}, {%8,%9}, {%0,%1,%2,%3};"
                 : "+f"(c[0]), "+f"(c[1]), "+f"(c[2]), "+f"(c[3])
                 : "r"(a[0]), "r"(a[1]), "r"(a[2]), "r"(a[3]), "r"(b0), "r"(b1));
}

#define CP_ASYNC16(dst, src) \
    asm volatile("cp.async.cg.shared.global [%0], [%1], 16;" \
                 :: "r"(dst), "l"(src) : "memory")
#define CP_COMMIT()  asm volatile("cp.async.commit_group;" ::: "memory")
#define CP_WAIT0()   asm volatile("cp.async.wait_group 0;" ::: "memory")

#define STS64(addr, v) \
    asm volatile("st.shared.b64 [%0], %1;" :: "r"(addr), "l"(v) : "memory")

// swizzled byte offset within a [rows x 128B] K-major bf16 tile:
// 16B unit u of row r goes to u ^ (r & 7)
__device__ __forceinline__ uint32_t swz_off(int r, int cb) {
    int u = cb >> 4;
    return (uint32_t)(r * 128 + (((u ^ (r & 7)) & 7) << 4) + (cb & 15));
}

__device__ __forceinline__ uint64_t pack_bf16x4(float a, float b, float c, float d) {
    __nv_bfloat162 lo = __floats2bfloat162_rn(a, b);
    __nv_bfloat162 hi = __floats2bfloat162_rn(c, d);
    uint32_t ulo = *(uint32_t*)&lo, uhi = *(uint32_t*)&hi;
    return (uint64_t)ulo | ((uint64_t)uhi << 32);
}

// ---------------- prep: pre-swizzled B + col biases (warp-parallel) ----------------
__global__ void prep_kernel(const float* __restrict__ pm, const float* __restrict__ pv) {
    int b = blockIdx.x, tid = threadIdx.x;
    if (b < 96) {
        int base = b * 1024;
        #pragma unroll
        for (int t = 0; t < 4; ++t) {
            int idx = base + t * 256 + tid;       // over 192*512
            int j = idx >> 9, d = idx & 511;
            float val = 0.0f;
            if (j < CMREAL)
                val = (d < 256) ? pm[j * 256 + d] : LAMDA * sqrtf(pv[j * 256 + (d - 256)]);
            int kc = d >> 6, k = d & 63;
            uint32_t off = swz_off(j, k * 2);
            *(__nv_bfloat16*)(g_B + kc * BCH_BYTES + off) = __float2bfloat16(val);
        }
    } else {
        // one warp per proto row j: lanes sum 8 elems each, shfl-reduce
        int wid = tid >> 5, lid = tid & 31;
        int j = (b - 96) * 8 + wid;               // 25 blocks x 8 warps = 200 >= 192
        if (j < CMPAD) {
            if (j < CMREAL) {
                const float2* p = (const float2*)(pv + j * 256);
                float2 v0 = p[lid * 4 + 0], v1 = p[lid * 4 + 1];
                float2 v2 = p[lid * 4 + 2], v3 = p[lid * 4 + 3];
                float s = v0.x + v0.y + v1.x + v1.y + v2.x + v2.y + v3.x + v3.y;
                #pragma unroll
                for (int o = 16; o > 0; o >>= 1)
                    s += __shfl_xor_sync(0xffffffffu, s, o);
                if (lid == 0) g_colbias[j] = -2.0f - LAMDA * s;
            } else if (lid == 0) {
                g_colbias[j] = 0.0f;
            }
        }
    }
}

// ---------------- main kernel (R14 structure, fully unrolled K loop) ----------------
extern __shared__ char smem_raw[];

__global__ void __launch_bounds__(THREADS, 2)
wasserstein_kernel(const float* __restrict__ x, const float* __restrict__ xv,
                   float* __restrict__ out) {
    const int tid = threadIdx.x;
    const int wid = tid >> 5;
    const int lid = tid & 31;
    const int warp_m = wid & 1;   // 2 x 32 rows
    const int warp_n = wid >> 1;  // 4 x 48 cols
    const int row0 = blockIdx.x * TILE_M;

    uint32_t sraw = smem_u32(smem_raw);
    uint32_t sbase = (sraw + 1023u) & ~1023u;
    char* smp = smem_raw + (sbase - sraw);

    float* sm_rs = (float*)(smp + OFF_RS);
    float* sm_cb = (float*)(smp + OFF_CB);
    const uint32_t uA[2] = { sbase + OFF_A0, sbase + OFF_A1 };
    const uint32_t uB[2] = { sbase + OFF_B0, sbase + OFF_B1 };

    if (tid < CMPAD) sm_cb[tid] = g_colbias[tid];

    const float4* x4 = (const float4*)x;
    const float4* v4 = (const float4*)xv;

    // per-thread A mapping: one row per thread-quad; 4 consecutive float4 each
    const int arow = tid >> 2;            // 0..63
    const int ac4  = (tid & 3) * 4;       // first float4 col within chunk (of 16)

    float acc[2][6][4];
    #pragma unroll
    for (int mi = 0; mi < 2; ++mi)
        #pragma unroll
        for (int nj = 0; nj < 6; ++nj)
            #pragma unroll
            for (int q = 0; q < 4; ++q) acc[mi][nj][q] = 0.0f;

    float4 aregs[4];
    float rsum = 0.0f;   // private partial row sum of x_var

    // ---- prologue: chunk 0 ----
    {
        const size_t rb = (size_t)(row0 + arow) * 64;
        #pragma unroll
        for (int i = 0; i < 4; ++i)
            aregs[i] = x4[rb + ac4 + i];
        const char* src = (const char*)g_B + tid * 16;
        #pragma unroll
        for (int i = 0; i < 6; ++i)
            CP_ASYNC16(uB[0] + tid * 16 + i * 4096, src + i * 4096);
        CP_COMMIT();
        #pragma unroll
        for (int i = 0; i < 4; ++i) {
            uint32_t off = swz_off(arow, (ac4 + i) * 8);
            STS64(uA[0] + off, pack_bf16x4(aregs[i].x, aregs[i].y, aregs[i].z, aregs[i].w));
        }
    }

    const int ra_base = warp_m * 32 + (lid & 15);
    const int a_uadd = lid >> 4;                       // +16B for hi K-half
    const int nb_base = warp_n * 48 + ((lid >> 4) << 3) + (lid & 7);
    const int b_uadd = (lid >> 3) & 1;

    // ---- main loop over 8 K-chunks (fully unrolled: all indices constant) ----
    #pragma unroll
    for (int kc = 0; kc < NCHUNKS; ++kc) {
        const int cur = kc & 1, nxt = cur ^ 1;
        CP_WAIT0();
        __syncthreads();

        const bool have_next = (kc < NCHUNKS - 1);
        if (have_next) {
            const int kn = kc + 1;
            const float4* srcT = (kn < 4) ? x4 : v4;
            const size_t rb = (size_t)(row0 + arow) * 64 + (kn & 3) * 16;
            #pragma unroll
            for (int i = 0; i < 4; ++i)
                aregs[i] = srcT[rb + ac4 + i];
            const char* src = (const char*)g_B + kn * BCH_BYTES + tid * 16;
            #pragma unroll
            for (int i = 0; i < 6; ++i)
                CP_ASYNC16(uB[nxt] + tid * 16 + i * 4096, src + i * 4096);
            CP_COMMIT();
        }

        // ---- MMA over chunk cur ----
        {
            const uint32_t ua = uA[cur], ub = uB[cur];
            #pragma unroll
            for (int ks = 0; ks < 4; ++ks) {
                uint32_t af[2][4];
                #pragma unroll
                for (int mi = 0; mi < 2; ++mi) {
                    int r = ra_base + mi * 16;
                    int u = ks * 2 + a_uadd;
                    ldm_x4(af[mi], ua + r * 128 + (((u ^ (r & 7)) & 7) << 4));
                }
                #pragma unroll
                for (int njp = 0; njp < 3; ++njp) {
                    int n = nb_base + njp * 16;
                    int u = ks * 2 + b_uadd;
                    uint32_t bf[4];
                    ldm_x4(bf, ub + n * 128 + (((u ^ (n & 7)) & 7) << 4));
                    #pragma unroll
                    for (int mi = 0; mi < 2; ++mi) {
                        mma16816(acc[mi][2 * njp],     af[mi], bf[0], bf[1]);
                        mma16816(acc[mi][2 * njp + 1], af[mi], bf[2], bf[3]);
                    }
                }
            }
        }

        // ---- convert + STS next A chunk (sqrt.approx; rsum in register) ----
        if (have_next) {
            const bool isv = (kc + 1) >= 4;
            if (isv) {
                rsum += aregs[0].x + aregs[0].y + aregs[0].z + aregs[0].w
                      + aregs[1].x + aregs[1].y + aregs[1].z + aregs[1].w
                      + aregs[2].x + aregs[2].y + aregs[2].z + aregs[2].w
                      + aregs[3].x + aregs[3].y + aregs[3].z + aregs[3].w;
                #pragma unroll
                for (int i = 0; i < 4; ++i) {
                    aregs[i].x = fsqrt_ap(aregs[i].x); aregs[i].y = fsqrt_ap(aregs[i].y);
                    aregs[i].z = fsqrt_ap(aregs[i].z); aregs[i].w = fsqrt_ap(aregs[i].w);
                }
            }
            #pragma unroll
            for (int i = 0; i < 4; ++i) {
                uint32_t off = swz_off(arow, (ac4 + i) * 8);
                STS64(uA[nxt] + off, pack_bf16x4(aregs[i].x, aregs[i].y, aregs[i].z, aregs[i].w));
            }
        }
    }

    // finalize row sums: reduce the 4 threads sharing a row; single plain store
    rsum += __shfl_xor_sync(0xffffffffu, rsum, 1);
    rsum += __shfl_xor_sync(0xffffffffu, rsum, 2);
    if ((lid & 3) == 0) sm_rs[arow] = rsum;

    __syncthreads();   // rowsums visible; MMA done

    // ---- epilogue: biases + direct guarded STG.64 from fragment layout ----
    {
        const int gid = lid >> 2, qid = lid & 3;
        #pragma unroll
        for (int mi = 0; mi < 2; ++mi) {
            int r = warp_m * 32 + mi * 16 + gid;
            float rb0 = -LAMDA * sm_rs[r];
            float rb1 = -LAMDA * sm_rs[r + 8];
            size_t g0 = (size_t)(row0 + r) * CMREAL;
            size_t g1 = (size_t)(row0 + r + 8) * CMREAL;
            #pragma unroll
            for (int nj = 0; nj < 6; ++nj) {
                int c = warp_n * 48 + nj * 8 + qid * 2;
                if (c < CMREAL) {
                    float cb0 = sm_cb[c], cb1 = sm_cb[c + 1];
                    float2 v0 = make_float2(2.0f * acc[mi][nj][0] + rb0 + cb0,
                                            2.0f * acc[mi][nj][1] + rb0 + cb1);
                    float2 v1 = make_float2(2.0f * acc[mi][nj][2] + rb1 + cb0,
                                            2.0f * acc[mi][nj][3] + rb1 + cb1);
                    *(float2*)(out + g0 + c) = v0;
                    *(float2*)(out + g1 + c) = v1;
                }
            }
        }
    }
}

// ---------------- launch ----------------
extern "C" void kernel_launch(void* const* d_in, const int* in_sizes, int n_in,
                              void* d_out, int out_size) {
    const float* x  = (const float*)d_in[0];
    const float* xv = (const float*)d_in[1];
    const float* pm = (const float*)d_in[2];
    const float* pv = (const float*)d_in[3];
    float* out = (float*)d_out;

    cudaFuncSetAttribute(wasserstein_kernel,
                         cudaFuncAttributeMaxDynamicSharedMemorySize, SMEM_REQ);

    prep_kernel<<<121, 256>>>(pm, pv);
    wasserstein_kernel<<<NROWS / TILE_M, THREADS, SMEM_REQ>>>(x, xv, out);
}